// round 11
// baseline (speedup 1.0000x reference)
#include <cuda_runtime.h>
#include <cuda_bf16.h>
#include <cstdint>

// Shapes (fixed): pointcloud (4,16384,3) f32; keys (4096,3) f32; values (4096,64) f32
// Output f32: feats (65536,64) | ids (65536) | pointcloud (196608) = 4456448 elems

#define BN       65536
#define M_KEYS   4096
#define D_FEAT   64
#define PC_ELEMS 196608

#define FEATS_OFF 0
#define IDS_OFF   4194304
#define PC_OFF    4259840

#define G        24
#define NCELLS   (G * G * G)            // 13824
#define BOX      4.75f
#define CELLW    (9.5f / 24.0f)         // 0.3958333
#define INVW     (24.0f / 9.5f)
// Reference d2 chain abs rounding error <= ~3e-5 at these magnitudes.
#define MARGIN   1e-3f

#define CAP      1024                    // staged-key cap (core 27-cell union ~360)

typedef unsigned long long ull;

// Device scratch (no allocs allowed in kernel_launch).
__device__ int    g_khist[NCELLS];
__device__ int    g_phist[NCELLS];
__device__ int    g_kstart[NCELLS + 1];
__device__ int    g_kcur[NCELLS];
__device__ int    g_pstart[NCELLS + 1];
__device__ int    g_pcur[NCELLS];
__device__ float4 g_skeys[M_KEYS];       // (x, y, z, ||k||^2), cell-sorted
__device__ int    g_skidx[M_KEYS];       // original key index
__device__ float4 g_spts[BN];            // (x, y, z, bitcast orig point idx)
__device__ int    g_ids[BN];             // result ids by original point index

__device__ __forceinline__ int cell_coord(float x) {
    int c = (int)floorf((x + BOX) * INVW);
    return min(max(c, 0), G - 1);
}

// ---------------------------------------------------------------------------
__global__ void __launch_bounds__(256) zero_kernel() {
    int t = blockIdx.x * blockDim.x + threadIdx.x;
    if (t < NCELLS) { g_khist[t] = 0; g_phist[t] = 0; }
}

// ---------------------------------------------------------------------------
__global__ void __launch_bounds__(256) hist_kernel(
    const float* __restrict__ pc, const float* __restrict__ keys)
{
    int t = blockIdx.x * blockDim.x + threadIdx.x;
    if (t < BN) {
        int cx = cell_coord(pc[3*t+0]);
        int cy = cell_coord(pc[3*t+1]);
        int cz = cell_coord(pc[3*t+2]);
        atomicAdd(&g_phist[(cz * G + cy) * G + cx], 1);
    }
    if (t < M_KEYS) {
        int cx = cell_coord(keys[3*t+0]);
        int cy = cell_coord(keys[3*t+1]);
        int cz = cell_coord(keys[3*t+2]);
        atomicAdd(&g_khist[(cz * G + cy) * G + cx], 1);
    }
}

// ---------------------------------------------------------------------------
// Exclusive scan, 2 blocks (keys / points), 1024 threads, 14 cells/thread.
// ---------------------------------------------------------------------------
#define CHK 14
__global__ void __launch_bounds__(1024) scan_kernel() {
    const bool isK = (blockIdx.x == 0);
    int* hist  = isK ? g_khist  : g_phist;
    int* start = isK ? g_kstart : g_pstart;
    int* cur   = isK ? g_kcur   : g_pcur;

    int t = threadIdx.x;
    int s = 0;
#pragma unroll
    for (int i = 0; i < CHK; ++i) {
        int idx = t * CHK + i;
        if (idx < NCELLS) s += hist[idx];
    }

    __shared__ int sm[1024];
    sm[t] = s;
    __syncthreads();
    for (int off = 1; off < 1024; off <<= 1) {
        int v = (t >= off) ? sm[t - off] : 0;
        __syncthreads();
        sm[t] += v;
        __syncthreads();
    }
    int run = sm[t] - s;

#pragma unroll
    for (int i = 0; i < CHK; ++i) {
        int idx = t * CHK + i;
        if (idx < NCELLS) {
            start[idx] = run;
            cur[idx]   = run;
            run += hist[idx];
        }
    }
    if (t == 1023) start[NCELLS] = sm[1023];
}

// ---------------------------------------------------------------------------
__global__ void __launch_bounds__(256) scatter_kernel(
    const float* __restrict__ pc, const float* __restrict__ keys)
{
    int t = blockIdx.x * blockDim.x + threadIdx.x;
    if (t < BN) {
        float x = pc[3*t+0], y = pc[3*t+1], z = pc[3*t+2];
        int c = (cell_coord(z) * G + cell_coord(y)) * G + cell_coord(x);
        int pos = atomicAdd(&g_pcur[c], 1);
        g_spts[pos] = make_float4(x, y, z, __int_as_float(t));
    }
    if (t < M_KEYS) {
        float kx = keys[3*t+0], ky = keys[3*t+1], kz = keys[3*t+2];
        float q = fmaf(kz, kz, fmaf(ky, ky, kx * kx));   // identical ksq chain
        int c = (cell_coord(kz) * G + cell_coord(ky)) * G + cell_coord(kx);
        int pos = atomicAdd(&g_kcur[c], 1);
        g_skeys[pos] = make_float4(kx, ky, kz, q);
        g_skidx[pos] = t;
    }
}

// ---------------------------------------------------------------------------
__device__ __forceinline__ float axis_dist(float p, int c) {
    float lo = (c == 0)     ? -1e30f : (-BOX + (float)c * CELLW);
    float hi = (c == G - 1) ?  1e30f : (-BOX + (float)(c + 1) * CELLW);
    return fmaxf(0.0f, fmaxf(lo - p, p - hi));
}

// ---------------------------------------------------------------------------
// K5: one block per key-cell. Block stages the 3x3x3 neighborhood key list
// to smem ONCE, then every point of the cell scans the same list with a
// uniform (broadcast) loop — zero divergence. Exact reference d2 chain per
// key; lexicographic (d2, idx) update (order-free => staging order is
// irrelevant). Per-point safety net: if best + MARGIN > rb^2 (rb = distance
// to 3x3x3 region boundary, inf at grid edges since boundary cells hold
// clamped keys), run the validated expanding-shell walk from r=2.
// ---------------------------------------------------------------------------
__global__ void __launch_bounds__(256) argmin_cell_kernel()
{
    int c = blockIdx.x;
    int p0 = g_pstart[c];
    int p1 = g_pstart[c + 1];
    if (p0 == p1) return;   // uniform early exit (before any sync)

    int cz = c / (G * G);
    int cy = (c / G) % G;
    int cx = c % G;

    __shared__ float4 s_k[CAP];
    __shared__ int    s_j[CAP];
    __shared__ int    s_r0[27], s_rl[27], s_ro[27];
    __shared__ int    s_total;

    int tid = threadIdx.x;

    // Gather the 27 neighbor cell ranges.
    if (tid < 27) {
        int dz = tid / 9 - 1, dy = (tid / 3) % 3 - 1, dx = tid % 3 - 1;
        int zz = cz + dz, yy = cy + dy, xx = cx + dx;
        int s0 = 0, len = 0;
        if (zz >= 0 && zz < G && yy >= 0 && yy < G && xx >= 0 && xx < G) {
            int cc = (zz * G + yy) * G + xx;
            s0 = g_kstart[cc];
            len = g_kstart[cc + 1] - s0;
        }
        s_r0[tid] = s0;
        s_rl[tid] = len;
    }
    __syncthreads();
    if (tid == 0) {
        int off = 0;
#pragma unroll
        for (int r = 0; r < 27; ++r) { s_ro[r] = off; off += s_rl[r]; }
        s_total = off;
    }
    __syncthreads();

    const int total = s_total;
    const bool ovf = (total > CAP);
    if (!ovf) {
#pragma unroll 1
        for (int r = 0; r < 27; ++r) {
            int len = s_rl[r], off = s_ro[r], s0 = s_r0[r];
            for (int i = tid; i < len; i += 256) {
                s_k[off + i] = g_skeys[s0 + i];
                s_j[off + i] = g_skidx[s0 + i];
            }
        }
        __syncthreads();
    }

    // Region outer boundary (inf at grid edges / clamped sides).
    float xlo = (cx <= 1)     ? -1e30f : (-BOX + (float)(cx - 1) * CELLW);
    float xhi = (cx >= G - 2) ?  1e30f : (-BOX + (float)(cx + 2) * CELLW);
    float ylo = (cy <= 1)     ? -1e30f : (-BOX + (float)(cy - 1) * CELLW);
    float yhi = (cy >= G - 2) ?  1e30f : (-BOX + (float)(cy + 2) * CELLW);
    float zlo = (cz <= 1)     ? -1e30f : (-BOX + (float)(cz - 1) * CELLW);
    float zhi = (cz >= G - 2) ?  1e30f : (-BOX + (float)(cz + 2) * CELLW);

    for (int ps = p0 + tid; ps < p1; ps += 256) {
        float4 p4 = g_spts[ps];
        float px = p4.x, py = p4.y, pz = p4.z;
        int orig = __float_as_int(p4.w);
        float psq = fmaf(pz, pz, fmaf(py, py, px * px));

        float best = __int_as_float(0x7f800000);   // +inf
        int   bidx = 0;

        if (!ovf) {
            // Uniform smem scan — all threads read the same address.
#pragma unroll 2
            for (int i = 0; i < total; ++i) {
                float4 k = s_k[i];
                float cross = fmaf(pz, k.z, fmaf(py, k.y, px * k.x));
                float d2 = fmaf(-2.0f, cross, psq) + k.w;
                int j = s_j[i];
                if (d2 < best || (d2 == best && j < bidx)) { best = d2; bidx = j; }
            }
        } else {
            for (int r = 0; r < 27; ++r) {
                int s0 = s_r0[r], s1 = s0 + s_rl[r];
                for (int s = s0; s < s1; ++s) {
                    float4 k = g_skeys[s];
                    float cross = fmaf(pz, k.z, fmaf(py, k.y, px * k.x));
                    float d2 = fmaf(-2.0f, cross, psq) + k.w;
                    int j = g_skidx[s];
                    if (d2 < best || (d2 == best && j < bidx)) { best = d2; bidx = j; }
                }
            }
        }

        // Safety net: region might not contain the true NN (sparse tail).
        float rb = fminf(fminf(px - xlo, xhi - px),
                  fminf(fminf(py - ylo, yhi - py),
                        fminf(pz - zlo, zhi - pz)));
        if (best + MARGIN > rb * rb) {
            // Expanding shells r>=2 (r<=1 == region, already scanned).
            for (int r = 2; r < G; ++r) {
                float lbr = (float)(r - 1) * CELLW;
                if (lbr * lbr > best + MARGIN) break;
                int zl = max(cz - r, 0), zh = min(cz + r, G - 1);
                for (int cz2 = zl; cz2 <= zh; ++cz2) {
                    int az = abs(cz2 - cz);
                    float azd = axis_dist(pz, cz2);
                    int yl = max(cy - r, 0), yh = min(cy + r, G - 1);
                    for (int cy2 = yl; cy2 <= yh; ++cy2) {
                        int ayz = max(az, abs(cy2 - cy));
                        float ay = axis_dist(py, cy2);
                        int xl = max(cx - r, 0), xh = min(cx + r, G - 1);
                        for (int cx2 = xl; cx2 <= xh; ++cx2) {
                            if (max(ayz, abs(cx2 - cx)) != r) continue;
                            float ax = axis_dist(px, cx2);
                            float lb2 = fmaf(ax, ax, fmaf(ay, ay, azd * azd));
                            if (lb2 > best + MARGIN) continue;
                            int cc = (cz2 * G + cy2) * G + cx2;
                            int s0 = g_kstart[cc], s1 = g_kstart[cc + 1];
                            for (int s = s0; s < s1; ++s) {
                                float4 k = g_skeys[s];
                                float cross = fmaf(pz, k.z, fmaf(py, k.y, px * k.x));
                                float d2 = fmaf(-2.0f, cross, psq) + k.w;
                                int j = g_skidx[s];
                                if (d2 < best || (d2 == best && j < bidx)) { best = d2; bidx = j; }
                            }
                        }
                    }
                }
            }
        }

        g_ids[orig] = bidx;
    }
}

// ---------------------------------------------------------------------------
// K6: gather values rows into feats + emit ids + copy pointcloud (proven).
// ---------------------------------------------------------------------------
__global__ void __launch_bounds__(256) gather_kernel(
    const float* __restrict__ pc,
    const float* __restrict__ values,
    float* __restrict__ out)
{
    int t = blockIdx.x * blockDim.x + threadIdx.x;

    if (t < PC_ELEMS / 4) {
        reinterpret_cast<float4*>(out + PC_OFF)[t] =
            reinterpret_cast<const float4*>(pc)[t];
    }

    int point = t >> 4;
    int q     = t & 15;
    if (point >= BN) return;

    int id = g_ids[point];
    if (q == 0) out[IDS_OFF + point] = (float)id;

    const float4* src = reinterpret_cast<const float4*>(values + (size_t)id * D_FEAT);
    float4* dst = reinterpret_cast<float4*>(out + FEATS_OFF + (size_t)point * D_FEAT);
    dst[q] = src[q];
}

// ---------------------------------------------------------------------------
extern "C" void kernel_launch(void* const* d_in, const int* in_sizes, int n_in,
                              void* d_out, int out_size) {
    const float* pc     = (const float*)d_in[0];
    const float* keys   = (const float*)d_in[1];
    const float* values = (const float*)d_in[2];
    float* out = (float*)d_out;

    zero_kernel<<<(NCELLS + 255) / 256, 256>>>();
    hist_kernel<<<(BN + 255) / 256, 256>>>(pc, keys);
    scan_kernel<<<2, 1024>>>();
    scatter_kernel<<<(BN + 255) / 256, 256>>>(pc, keys);
    argmin_cell_kernel<<<NCELLS, 256>>>();
    gather_kernel<<<(BN * 16 + 255) / 256, 256>>>(pc, values, out);
}

// round 12
// speedup vs baseline: 1.7212x; 1.7212x over previous
#include <cuda_runtime.h>
#include <cuda_bf16.h>
#include <cstdint>

// Shapes (fixed): pointcloud (4,16384,3) f32; keys (4096,3) f32; values (4096,64) f32
// Output f32: feats (65536,64) | ids (65536) | pointcloud (196608) = 4456448 elems

#define BN       65536
#define M_KEYS   4096
#define D_FEAT   64
#define PC_ELEMS 196608

#define FEATS_OFF 0
#define IDS_OFF   4194304
#define PC_OFF    4259840

// Morton grid for point sorting only (keys stay unsorted).
#define G        32
#define NCELLS   32768
#define BOX      4.75f
#define INVW     (32.0f / 9.5f)

#define CAP      2048        // candidate capacity (smem)
#define SAFE     0.02f       // geometric cull slack; >>100x all fp rounding
#define PTS_BLK  256         // points per argmin block
#define ATPB     512         // argmin threads per block (2 lanes/point)

typedef unsigned long long ull;

// Device scratch (no allocs allowed in kernel_launch).
__device__ int    g_phist[NCELLS];
__device__ int    g_pcur[NCELLS];
__device__ float4 g_spts[BN];    // (x, y, z, bitcast orig point idx), Morton-sorted

// ---------------------------------------------------------------------------
// Morton helpers: spread 5 bits to every 3rd position.
// ---------------------------------------------------------------------------
__device__ __forceinline__ unsigned mpart(unsigned x) {
    x &= 31u;
    x = (x | (x << 8)) & 0x100Fu;
    x = (x | (x << 4)) & 0x10C3u;
    x = (x | (x << 2)) & 0x1249u;
    return x;
}
__device__ __forceinline__ int cellc(float x) {
    int c = (int)floorf((x + BOX) * INVW);
    return min(max(c, 0), G - 1);
}
__device__ __forceinline__ int morton_cell(float x, float y, float z) {
    return (int)(mpart(cellc(x)) | (mpart(cellc(y)) << 1) | (mpart(cellc(z)) << 2));
}

// ---------------------------------------------------------------------------
// K1: zero point histogram.
// ---------------------------------------------------------------------------
__global__ void __launch_bounds__(256) zero_kernel() {
    int t = blockIdx.x * blockDim.x + threadIdx.x;
    if (t < NCELLS) g_phist[t] = 0;
}

// ---------------------------------------------------------------------------
// K2: point histogram + pointcloud copy (folded).
// ---------------------------------------------------------------------------
__global__ void __launch_bounds__(256) hist_kernel(
    const float* __restrict__ pc, float* __restrict__ out)
{
    int t = blockIdx.x * blockDim.x + threadIdx.x;
    if (t < PC_ELEMS / 4) {
        reinterpret_cast<float4*>(out + PC_OFF)[t] =
            reinterpret_cast<const float4*>(pc)[t];
    }
    if (t < BN) {
        int c = morton_cell(pc[3*t+0], pc[3*t+1], pc[3*t+2]);
        atomicAdd(&g_phist[c], 1);
    }
}

// ---------------------------------------------------------------------------
// K3: exclusive scan of point histogram. 1 block, 1024 threads x 32 cells.
// ---------------------------------------------------------------------------
__global__ void __launch_bounds__(1024) scan_kernel() {
    int t = threadIdx.x;
    int s = 0;
#pragma unroll
    for (int i = 0; i < 32; ++i) s += g_phist[t * 32 + i];

    __shared__ int sm[1024];
    sm[t] = s;
    __syncthreads();
    for (int off = 1; off < 1024; off <<= 1) {
        int v = (t >= off) ? sm[t - off] : 0;
        __syncthreads();
        sm[t] += v;
        __syncthreads();
    }
    int run = sm[t] - s;
#pragma unroll
    for (int i = 0; i < 32; ++i) {
        int idx = t * 32 + i;
        g_pcur[idx] = run;
        run += g_phist[idx];
    }
}

// ---------------------------------------------------------------------------
// K4: scatter points into Morton-sorted order. Within-cell order is
// nondeterministic (atomic) but output-invariant: the argmin result per
// point is independent of block composition (cull proof holds per-bbox).
// ---------------------------------------------------------------------------
__global__ void __launch_bounds__(256) scatter_kernel(const float* __restrict__ pc)
{
    int t = blockIdx.x * blockDim.x + threadIdx.x;
    if (t < BN) {
        float x = pc[3*t+0], y = pc[3*t+1], z = pc[3*t+2];
        int c = morton_cell(x, y, z);
        int pos = atomicAdd(&g_pcur[c], 1);
        g_spts[pos] = make_float4(x, y, z, __int_as_float(t));
    }
}

// Order-preserving float->u32.
__device__ __forceinline__ unsigned ordu(float f) {
    unsigned u = __float_as_uint(f);
    return (u & 0x80000000u) ? ~u : (u | 0x80000000u);
}

// ---------------------------------------------------------------------------
// K5: block-culled brute argmin + fused gather.
// Block = 256 Morton-adjacent points, 512 threads (2 lanes/point).
//   1) bbox of the block's points -> center c, radius r.
//   2) block scans ALL keys: dmin2 = min d(c,k)^2 (geometric only).
//   3) cull: keep k iff d(c,k) <= sqrt(dmin2) + 2r + SAFE.
//      Proof of safety: for any p in bbox, d(p,k) >= d(c,k)-r and
//      NN(p) <= sqrt(dmin2)+r, so a culled key is > SAFE farther than a
//      known key; SAFE^2 = 4e-4 >> 2x the 3e-5 exact-chain rounding, so it
//      cannot win or tie under the reference d2 chain.
//   4) uniform smem scan of candidates with the exact reference chain:
//      cross = fmaf(pz,kz,fmaf(py,ky,px*kx)); d2 = fmaf(-2,cross,psq)+ksq
//      lexicographic (d2, idx) update == jnp.argmin first-min (order-free).
//   5) overflow (>CAP, rare tail blocks): block-uniform chunked smem brute
//      over all 4096 keys (exact).
//   6) pair-merge lanes via shfl; write ids + gather values row (fused).
// ---------------------------------------------------------------------------
__global__ void __launch_bounds__(ATPB) argmin_cull_kernel(
    const float* __restrict__ keys,
    const float* __restrict__ values,
    float* __restrict__ out)
{
    __shared__ float4 s_k[CAP];
    __shared__ int    s_j[CAP];
    __shared__ float  s_red[ATPB];
    __shared__ int    s_count;

    const int tid = threadIdx.x;
    const int q   = tid & 1;
    const int ps  = blockIdx.x * PTS_BLK + (tid >> 1);

    float4 p4 = g_spts[ps];
    const float px = p4.x, py = p4.y, pz = p4.z;
    const int orig = __float_as_int(p4.w);

    // --- block min helper (inlined 3x min, 3x max via negation, 1x dmin) ---
#define BLK_MIN(INVAL, OUTVAL)                                              \
    do {                                                                     \
        s_red[tid] = (INVAL);                                                \
        __syncthreads();                                                     \
        for (int o = ATPB / 2; o > 0; o >>= 1) {                             \
            if (tid < o) s_red[tid] = fminf(s_red[tid], s_red[tid + o]);     \
            __syncthreads();                                                 \
        }                                                                    \
        (OUTVAL) = s_red[0];                                                 \
        __syncthreads();                                                     \
    } while (0)

    float xlo, xhi, ylo, yhi, zlo, zhi;
    BLK_MIN(px, xlo);  BLK_MIN(-px, xhi);  xhi = -xhi;
    BLK_MIN(py, ylo);  BLK_MIN(-py, yhi);  yhi = -yhi;
    BLK_MIN(pz, zlo);  BLK_MIN(-pz, zhi);  zhi = -zhi;

    const float cx = 0.5f * (xlo + xhi);
    const float cy = 0.5f * (ylo + yhi);
    const float cz = 0.5f * (zlo + zhi);
    const float hx = 0.5f * (xhi - xlo), hy = 0.5f * (yhi - ylo), hz = 0.5f * (zhi - zlo);
    const float r  = sqrtf(fmaf(hx, hx, fmaf(hy, hy, hz * hz)));

    // Pass A: min distance^2 from bbox center to any key (geometric).
    float mymin = 1e30f;
    for (int j = tid; j < M_KEYS; j += ATPB) {
        float dx = keys[3*j+0] - cx;
        float dy = keys[3*j+1] - cy;
        float dz = keys[3*j+2] - cz;
        mymin = fminf(mymin, fmaf(dx, dx, fmaf(dy, dy, dz * dz)));
    }
    float dmin2;
    BLK_MIN(mymin, dmin2);

    const float thr  = sqrtf(dmin2) + 2.0f * r + SAFE;
    const float thr2 = thr * thr;

    // Pass B: compact surviving candidates to smem.
    if (tid == 0) s_count = 0;
    __syncthreads();
    for (int j = tid; j < M_KEYS; j += ATPB) {
        float kx = keys[3*j+0], ky = keys[3*j+1], kz = keys[3*j+2];
        float dx = kx - cx, dy = ky - cy, dz = kz - cz;
        float d2c = fmaf(dx, dx, fmaf(dy, dy, dz * dz));
        if (d2c <= thr2) {
            int pos = atomicAdd(&s_count, 1);
            if (pos < CAP) {
                float ksq = fmaf(kz, kz, fmaf(ky, ky, kx * kx));  // exact chain
                s_k[pos] = make_float4(kx, ky, kz, ksq);
                s_j[pos] = j;
            }
        }
    }
    __syncthreads();
    const int count = s_count;

    const float psq = fmaf(pz, pz, fmaf(py, py, px * px));
    float best = __int_as_float(0x7f800000);   // +inf
    int   bidx = 0;

    if (count <= CAP) {
        // Uniform candidate scan: 2 lanes per point, stride 2.
        for (int i = q; i < count; i += 2) {
            float4 k = s_k[i];
            float cross = fmaf(pz, k.z, fmaf(py, k.y, px * k.x));
            float d2 = fmaf(-2.0f, cross, psq) + k.w;
            int j = s_j[i];
            if (d2 < best || (d2 == best && j < bidx)) { best = d2; bidx = j; }
        }
    } else {
        // Rare: chunked exact brute over all keys (block-uniform branch).
        for (int base = 0; base < M_KEYS; base += CAP) {
            __syncthreads();
            for (int i = tid; i < CAP; i += ATPB) {
                int j = base + i;
                float kx = keys[3*j+0], ky = keys[3*j+1], kz = keys[3*j+2];
                float ksq = fmaf(kz, kz, fmaf(ky, ky, kx * kx));
                s_k[i] = make_float4(kx, ky, kz, ksq);
            }
            __syncthreads();
            for (int i = q; i < CAP; i += 2) {
                float4 k = s_k[i];
                float cross = fmaf(pz, k.z, fmaf(py, k.y, px * k.x));
                float d2 = fmaf(-2.0f, cross, psq) + k.w;
                int j = base + i;
                if (d2 < best || (d2 == best && j < bidx)) { best = d2; bidx = j; }
            }
        }
    }

    // Merge the point's two lanes: lexicographic (ordered d2, idx) min.
    ull packed = ((ull)ordu(best) << 32) | (unsigned)bidx;
    ull other = __shfl_xor_sync(0xFFFFFFFFu, packed, 1);
    packed = min(packed, other);
    bidx = (int)(packed & 0xFFFFFFFFu);

    // Fused output: id + values row (8 float4 per lane).
    if (q == 0) out[IDS_OFF + orig] = (float)bidx;
    const float4* src = reinterpret_cast<const float4*>(values + (size_t)bidx * D_FEAT);
    float4* dst = reinterpret_cast<float4*>(out + FEATS_OFF + (size_t)orig * D_FEAT);
#pragma unroll
    for (int i = 0; i < 8; ++i)
        dst[q * 8 + i] = src[q * 8 + i];
}

// ---------------------------------------------------------------------------
extern "C" void kernel_launch(void* const* d_in, const int* in_sizes, int n_in,
                              void* d_out, int out_size) {
    const float* pc     = (const float*)d_in[0];
    const float* keys   = (const float*)d_in[1];
    const float* values = (const float*)d_in[2];
    float* out = (float*)d_out;

    zero_kernel<<<NCELLS / 256, 256>>>();
    hist_kernel<<<(BN + 255) / 256, 256>>>(pc, out);
    scan_kernel<<<1, 1024>>>();
    scatter_kernel<<<(BN + 255) / 256, 256>>>(pc);
    argmin_cull_kernel<<<BN / PTS_BLK, ATPB>>>(keys, values, out);
}

// round 14
// speedup vs baseline: 5.6663x; 3.2921x over previous
#include <cuda_runtime.h>
#include <cuda_bf16.h>
#include <cstdint>

// Shapes (fixed): pointcloud (4,16384,3) f32; keys (4096,3) f32; values (4096,64) f32
// Output f32: feats (65536,64) | ids (65536) | pointcloud (196608) = 4456448 elems

#define BN       65536
#define M_KEYS   4096
#define D_FEAT   64
#define PC_ELEMS 196608

#define FEATS_OFF 0
#define IDS_OFF   4194304
#define PC_OFF    4259840

#define NSLICE   8
#define SLICE_M  (M_KEYS / NSLICE)      // 512 keys per slice
#define SLICE_P  (SLICE_M / 2)          // 256 key-pairs per slice

#define TPB      128                     // threads per block (argmin)
#define PPT      4                       // points per thread
#define PTS_BLK  (TPB * PPT)             // 512 points per block -> 1024 blocks

typedef unsigned long long ull;

// ---- packed f32x2 helpers (each half = exact scalar fp32 op) ----
#define FMA2(out, a, b, c) \
    asm("fma.rn.f32x2 %0, %1, %2, %3;" : "=l"(out) : "l"(a), "l"(b), "l"(c))
#define MUL2(out, a, b) \
    asm("mul.rn.f32x2 %0, %1, %2;" : "=l"(out) : "l"(a), "l"(b))
#define ADD2(out, a, b) \
    asm("add.rn.f32x2 %0, %1, %2;" : "=l"(out) : "l"(a), "l"(b))
#define PACK2(out, lo, hi) \
    asm("mov.b64 %0, {%1, %2};" : "=l"(out) : "f"(lo), "f"(hi))
#define UNPACK2(lo, hi, in) \
    asm("mov.b64 {%0, %1}, %2;" : "=f"(lo), "=f"(hi) : "l"(in))

// Key-pair struct: a = (kx0,kx1,ky0,ky1), b = (kz0,kz1,ksq0,ksq1)
struct KeyPair { float4 a; float4 b; };

// Device scratch (no allocs allowed in kernel_launch).
__device__ KeyPair g_kp[M_KEYS / 2];
__device__ ull g_best[BN];   // (ordered_d2_bits << 32) | key_idx

// ---------------------------------------------------------------------------
// Kernel 0: fused prep (key pairs + ||k||^2) and best-init.  (R5-proven)
// ---------------------------------------------------------------------------
__global__ void __launch_bounds__(256) prep_kernel(const float* __restrict__ keys) {
    int t = blockIdx.x * blockDim.x + threadIdx.x;
    if (t < BN) g_best[t] = 0xFFFFFFFFFFFFFFFFULL;
    if (t < M_KEYS / 2) {
        int j0 = 2 * t;
        float kx0 = keys[3*j0+0], ky0 = keys[3*j0+1], kz0 = keys[3*j0+2];
        float kx1 = keys[3*j0+3], ky1 = keys[3*j0+4], kz1 = keys[3*j0+5];
        float q0 = fmaf(kz0, kz0, fmaf(ky0, ky0, kx0 * kx0));
        float q1 = fmaf(kz1, kz1, fmaf(ky1, ky1, kx1 * kx1));
        KeyPair kp;
        kp.a = make_float4(kx0, kx1, ky0, ky1);
        kp.b = make_float4(kz0, kz1, q0, q1);
        g_kp[t] = kp;
    }
}

// ---------------------------------------------------------------------------
// Kernel 1: sliced argmin. Identical arithmetic and semantics to R5 (proven
// rel_err 0.0); single change: PPT=4 at TPB=128 (same 1024-block grid) to
// halve LDS issues per key-point — LDS was the measured binder.
// Per-half arithmetic (bit-exact form):
//   cross = fmaf(pz,kz, fmaf(py,ky, px*kx));  d2 = fmaf(-2,cross,psq) + ksq
// In-loop: dm = fminf(d0,d1); strict (dm < best) updates {best, iwin}.
// Post-loop: recompute winning pair (identical chain -> bit-identical),
// resolve half via (d1 < d0); strict '<' ascending == jnp.argmin first-min.
// Cross-slice merge via lexicographic u64 atomicMin on (ordered_bits, idx).
// ---------------------------------------------------------------------------
__global__ void __launch_bounds__(TPB) argmin_slice_kernel(
    const float* __restrict__ pc)
{
    __shared__ KeyPair sk[SLICE_P];   // 8KB

    const int base = blockIdx.y * SLICE_M;

#pragma unroll
    for (int i = threadIdx.x; i < SLICE_P; i += TPB)
        sk[i] = g_kp[blockIdx.y * SLICE_P + i];
    __syncthreads();

    const int p0 = blockIdx.x * PTS_BLK + threadIdx.x;

    ull px2[PPT], py2[PPT], pz2[PPT], psq2[PPT], n22;
    PACK2(n22, -2.0f, -2.0f);
#pragma unroll
    for (int k = 0; k < PPT; ++k) {
        int p = p0 + k * TPB;
        float px = pc[3 * p + 0];
        float py = pc[3 * p + 1];
        float pz = pc[3 * p + 2];
        float psq = fmaf(pz, pz, fmaf(py, py, px * px));
        PACK2(px2[k], px, px);
        PACK2(py2[k], py, py);
        PACK2(pz2[k], pz, pz);
        PACK2(psq2[k], psq, psq);
    }

    float best[PPT];
    int   iwin[PPT];
#pragma unroll
    for (int k = 0; k < PPT; ++k) {
        best[k] = __int_as_float(0x7f800000);   // +inf
        iwin[k] = 0;
    }

#pragma unroll 2
    for (int i = 0; i < SLICE_P; ++i) {
        float4 a = sk[i].a;   // kx0,kx1,ky0,ky1
        float4 b = sk[i].b;   // kz0,kz1,q0,q1
        ull kx01, ky01, kz01, q01;
        PACK2(kx01, a.x, a.y);
        PACK2(ky01, a.z, a.w);
        PACK2(kz01, b.x, b.y);
        PACK2(q01,  b.z, b.w);

#pragma unroll
        for (int k = 0; k < PPT; ++k) {
            ull c, t, d;
            MUL2(c, px2[k], kx01);
            FMA2(c, py2[k], ky01, c);
            FMA2(c, pz2[k], kz01, c);
            FMA2(t, n22, c, psq2[k]);
            ADD2(d, t, q01);
            float d0, d1;
            UNPACK2(d0, d1, d);
            float dm = fminf(d0, d1);
            if (dm < best[k]) { best[k] = dm; iwin[k] = i; }
        }
    }

    // Post-loop half-bit recovery + packed merge.
#pragma unroll
    for (int k = 0; k < PPT; ++k) {
        int i = iwin[k];
        float4 a = sk[i].a;
        float4 b = sk[i].b;
        ull kx01, ky01, kz01, q01, c, t, d;
        PACK2(kx01, a.x, a.y);
        PACK2(ky01, a.z, a.w);
        PACK2(kz01, b.x, b.y);
        PACK2(q01,  b.z, b.w);
        MUL2(c, px2[k], kx01);
        FMA2(c, py2[k], ky01, c);
        FMA2(c, pz2[k], kz01, c);
        FMA2(t, n22, c, psq2[k]);
        ADD2(d, t, q01);
        float d0, d1;
        UNPACK2(d0, d1, d);
        int bidx = base + 2 * i + ((d1 < d0) ? 1 : 0);

        unsigned u = __float_as_uint(best[k]);
        u = (u & 0x80000000u) ? ~u : (u | 0x80000000u);
        ull packed = ((ull)u << 32) | (unsigned)bidx;
        atomicMin(&g_best[p0 + k * TPB], packed);
    }
}

// ---------------------------------------------------------------------------
// Kernel 2: gather values rows into feats + emit ids + copy pointcloud.
// 16 threads/point, float4 lanes.  (R5-proven)
// ---------------------------------------------------------------------------
__global__ void __launch_bounds__(256) gather_kernel(
    const float* __restrict__ pc,
    const float* __restrict__ values,
    float* __restrict__ out)
{
    int t = blockIdx.x * blockDim.x + threadIdx.x;

    if (t < PC_ELEMS / 4) {
        reinterpret_cast<float4*>(out + PC_OFF)[t] =
            reinterpret_cast<const float4*>(pc)[t];
    }

    int point = t >> 4;
    int q     = t & 15;
    if (point >= BN) return;

    int id = (int)(g_best[point] & 0xFFFFFFFFu);   // broadcast load
    if (q == 0) out[IDS_OFF + point] = (float)id;

    const float4* src = reinterpret_cast<const float4*>(values + (size_t)id * D_FEAT);
    float4* dst = reinterpret_cast<float4*>(out + FEATS_OFF + (size_t)point * D_FEAT);
    dst[q] = src[q];
}

// ---------------------------------------------------------------------------
extern "C" void kernel_launch(void* const* d_in, const int* in_sizes, int n_in,
                              void* d_out, int out_size) {
    const float* pc     = (const float*)d_in[0];
    const float* keys   = (const float*)d_in[1];
    const float* values = (const float*)d_in[2];
    float* out = (float*)d_out;

    prep_kernel<<<(BN + 255) / 256, 256>>>(keys);

    dim3 grid(BN / PTS_BLK, NSLICE);
    argmin_slice_kernel<<<grid, TPB>>>(pc);

    gather_kernel<<<(BN * 16 + 255) / 256, 256>>>(pc, values, out);
}